// round 9
// baseline (speedup 1.0000x reference)
#include <cuda_runtime.h>
#include <cstdint>

// Problem constants
#define BB   8
#define CIN  64
#define COUT 64
#define RN   4
#define HH   128
#define WW   128

// Tiling
#define TH   4            // output rows per block
#define TW   32           // output cols per block
#define XROWS 6           // TH + 2 halo
#define XP   36           // x smem pitch (16B-aligned rows, conflict-free LDS.128)
#define WPITCH 68         // W smem pitch (multiple of 4 -> aligned LDS.128 broadcast)
#define ICB  8            // ic chunk per W stage
#define NTHR 256
#define NSTAGE 32         // RN * (CIN/ICB)

#define SX_FLOATS (CIN*XROWS*XP)     // 13824
#define SWBUF     (ICB*9*WPITCH)     // 4896 per buffer
#define SM_FLOATS (RN*TH*TW)         // 512
#define SMEM_BYTES ((SX_FLOATS + 2*SWBUF + SM_FLOATS) * 4)   // 96512 B

#define MASK_BASE ((size_t)BB*COUT*HH*WW)   // 8388608

typedef unsigned long long u64;

__device__ __forceinline__ u64 pk2(float a, float b) {
    u64 r; asm("mov.b64 %0, {%1, %2};" : "=l"(r) : "f"(a), "f"(b)); return r;
}
__device__ __forceinline__ void up2(u64 v, float& a, float& b) {
    asm("mov.b64 {%0, %1}, %2;" : "=f"(a), "=f"(b) : "l"(v));
}
// packed dual-fp32 FMA (FFMA2): d = a*b + c lanewise
__device__ __forceinline__ u64 f2ma(u64 a, u64 b, u64 c) {
    u64 d; asm("fma.rn.f32x2 %0, %1, %2, %3;" : "=l"(d) : "l"(a), "l"(b), "l"(c)); return d;
}

__device__ __forceinline__ void cpa4(float* dst, const float* src) {
    unsigned s = (unsigned)__cvta_generic_to_shared(dst);
    asm volatile("cp.async.ca.shared.global [%0], [%1], 4;" :: "r"(s), "l"(src));
}
__device__ __forceinline__ void cpa_commit() {
    asm volatile("cp.async.commit_group;" ::: "memory");
}
__device__ __forceinline__ void cpa_wait0() {
    asm volatile("cp.async.wait_group 0;" ::: "memory");
}

// Prefetch one W stage (r = stage>>3, ic-chunk = stage&7) into buf, transposed
// to [tap(i*9+t)][oc] with pitch WPITCH. 4608 elems / 256 thr = 18 cp.async each.
__device__ __forceinline__ void prefetch_w(const float* kbase, int stage,
                                           float* buf, int tid) {
    const int rr = stage >> 3, cc = stage & 7;
    const float* kc = kbase + (size_t)rr * (COUT * CIN * 9) + cc * (ICB * 9);
    int e = tid;
    #pragma unroll
    for (int it = 0; it < 18; it++, e += NTHR) {
        int oc  = e / (ICB * 9);
        int rem = e - oc * (ICB * 9);          // i*9 + t
        cpa4(&buf[rem * WPITCH + oc], &kc[oc * (CIN * 9) + rem]);
    }
    cpa_commit();
}

extern "C" __global__ void __launch_bounds__(NTHR, 2)
hrc_kernel(const float* __restrict__ x,     const float* __restrict__ kern,
           const float* __restrict__ maskw, const float* __restrict__ maskb,
           const float* __restrict__ bn_g,  const float* __restrict__ bn_b,
           const float* __restrict__ bn_m,  const float* __restrict__ bn_v,
           float* __restrict__ out)
{
    extern __shared__ float smem[];
    float* sx  = smem;                    // [CIN][XROWS][XP]
    float* swA = smem + SX_FLOATS;        // W double buffer A (stage 0,2,...)
    float* swB = swA + SWBUF;             // W double buffer B (stage 1,3,...) / mask_w overlay
    float* sm  = swB + SWBUF;             // masks [RN][TH*TW]

    const int b   = blockIdx.z;
    const int h0  = blockIdx.y * TH;
    const int w0  = blockIdx.x * TW;
    const int tid = threadIdx.x;

    const float* kbase = kern + (size_t)b * RN * COUT * CIN * 9;

    // kick off W stage-0 prefetch immediately (lands in swA)
    prefetch_w(kbase, 0, swA, tid);

    // ---------------- load x tile (64 ch + halo), SAME zero-padding ----------------
    const float* xb = x + (size_t)b * CIN * HH * WW;
    for (int idx = tid; idx < CIN * XROWS * (TW + 2); idx += NTHR) {
        int ic  = idx / (XROWS * (TW + 2));
        int rem = idx - ic * (XROWS * (TW + 2));
        int r   = rem / (TW + 2);
        int c   = rem - r * (TW + 2);
        int gh = h0 - 1 + r, gw = w0 - 1 + c;
        float v = 0.f;
        if ((unsigned)gh < HH && (unsigned)gw < WW)
            v = xb[(ic * HH + gh) * WW + gw];
        sx[(ic * XROWS + r) * XP + c] = v;
    }
    // mask_w (2304 floats) overlaid into swB (stage-1 prefetch overwrites it later)
    for (int idx = tid; idx < RN * CIN * 9; idx += NTHR) swB[idx] = maskw[idx];
    __syncthreads();

    // ---------------- phase 1: region logits -> softmax masks ----------------
    {
        float* spart = swB + RN * CIN * 9;   // 512 floats scratch (2304+512 <= SWBUF)
        const int px   = tid & 127;
        const int half = tid >> 7;
        const int row = px >> 5, col = px & 31;
        float lg[RN] = {0.f, 0.f, 0.f, 0.f};
        const int ic_lo = half * (CIN / 2), ic_hi = ic_lo + CIN / 2;
        for (int ic = ic_lo; ic < ic_hi; ic++) {
            const float* xp = &sx[(ic * XROWS + row) * XP + col];
            float xv[9];
            #pragma unroll
            for (int kh = 0; kh < 3; kh++)
                #pragma unroll
                for (int kw = 0; kw < 3; kw++) xv[kh * 3 + kw] = xp[kh * XP + kw];
            #pragma unroll
            for (int r = 0; r < RN; r++) {
                const float* wp = &swB[(r * CIN + ic) * 9];
                #pragma unroll
                for (int t = 0; t < 9; t++) lg[r] = fmaf(wp[t], xv[t], lg[r]);
            }
        }
        if (half == 1) {
            #pragma unroll
            for (int r = 0; r < RN; r++) spart[r * 128 + px] = lg[r];
        }
        __syncthreads();
        if (half == 0) {
            #pragma unroll
            for (int r = 0; r < RN; r++) lg[r] += spart[r * 128 + px] + maskb[r];
            float mx = fmaxf(fmaxf(lg[0], lg[1]), fmaxf(lg[2], lg[3]));
            float e[RN]; float s = 0.f;
            #pragma unroll
            for (int r = 0; r < RN; r++) { e[r] = expf(lg[r] - mx); s += e[r]; }
            float inv = 1.f / s;
            #pragma unroll
            for (int r = 0; r < RN; r++) {
                float m = e[r] * inv;
                sm[r * (TH * TW) + px] = m;
                out[MASK_BASE + ((size_t)(b * RN + r) * HH + (h0 + row)) * WW + (w0 + col)] = m;
            }
        }
        __syncthreads();
    }

    // ---------------- phase 2: dynamic conv, region-folded, double-buffered W ----------------
    // Thread computes 8 oc (as 4 f32x2 pairs) x 4 px (along w).
    const int ocg8 = (tid >> 5) << 3;        // warp-uniform -> broadcast W reads
    const int pxg  = tid & 31;
    const int prow = pxg >> 3;               // 0..3
    const int pcol = (pxg & 7) << 2;         // 0,4,...,28

    u64 accF[4][4];
    const u64 Z = pk2(0.f, 0.f);
    #pragma unroll
    for (int j = 0; j < 4; j++)
        #pragma unroll
        for (int p = 0; p < 4; p++) accF[j][p] = Z;

    int stage = 0;
    for (int r = 0; r < RN; r++) {
        u64 accR[4][4];
        #pragma unroll
        for (int j = 0; j < 4; j++)
            #pragma unroll
            for (int p = 0; p < 4; p++) accR[j][p] = Z;

        for (int c = 0; c < CIN / ICB; c++, stage++) {
            float* cur = (stage & 1) ? swB : swA;
            float* nxt = (stage & 1) ? swA : swB;

            cpa_wait0();          // this stage's W has landed (locally)
            __syncthreads();      // ...and is visible; prior stage's readers done with nxt
            if (stage + 1 < NSTAGE) prefetch_w(kbase, stage + 1, nxt, tid);

            const int ic0 = c * ICB;
            #pragma unroll 2
            for (int i = 0; i < ICB; i++) {
                const float* xrow = &sx[((ic0 + i) * XROWS + prow) * XP + pcol];
                #pragma unroll
                for (int kh = 0; kh < 3; kh++) {
                    const float* xp = xrow + kh * XP;
                    float4 xa = *(const float4*)xp;         // cols pcol..pcol+3
                    float4 xc = *(const float4*)(xp + 4);   // cols pcol+4..pcol+7 (z,w unused)
                    u64 xx[6];
                    xx[0] = pk2(xa.x, xa.x); xx[1] = pk2(xa.y, xa.y);
                    xx[2] = pk2(xa.z, xa.z); xx[3] = pk2(xa.w, xa.w);
                    xx[4] = pk2(xc.x, xc.x); xx[5] = pk2(xc.y, xc.y);
                    const float* wrow = &cur[(i * 9 + kh * 3) * WPITCH + ocg8];
                    #pragma unroll
                    for (int kw = 0; kw < 3; kw++) {
                        const ulonglong2* wp = (const ulonglong2*)(wrow + kw * WPITCH);
                        ulonglong2 Wa = wp[0];   // oc pairs (0,1),(2,3)
                        ulonglong2 Wb = wp[1];   // oc pairs (4,5),(6,7)
                        #pragma unroll
                        for (int p = 0; p < 4; p++) {
                            u64 xv2 = xx[kw + p];
                            accR[0][p] = f2ma(Wa.x, xv2, accR[0][p]);
                            accR[1][p] = f2ma(Wa.y, xv2, accR[1][p]);
                            accR[2][p] = f2ma(Wb.x, xv2, accR[2][p]);
                            accR[3][p] = f2ma(Wb.y, xv2, accR[3][p]);
                        }
                    }
                }
            }
        }
        // fold this region with its mask weight
        #pragma unroll
        for (int p = 0; p < 4; p++) {
            float m = sm[r * (TH * TW) + prow * TW + pcol + p];
            u64 mm = pk2(m, m);
            #pragma unroll
            for (int j = 0; j < 4; j++) accF[j][p] = f2ma(mm, accR[j][p], accF[j][p]);
        }
    }

    // ---------------- epilogue: BN (eval) + ReLU, float4 stores ----------------
    const size_t obase = (size_t)b * COUT * HH * WW;
    const int gh  = h0 + prow;
    const int gwc = w0 + pcol;
    #pragma unroll
    for (int j = 0; j < 4; j++) {
        int oc0 = ocg8 + 2 * j;
        float i0 = bn_g[oc0]     / sqrtf(bn_v[oc0]     + 1e-5f);
        float i1 = bn_g[oc0 + 1] / sqrtf(bn_v[oc0 + 1] + 1e-5f);
        float m0 = bn_m[oc0], m1 = bn_m[oc0 + 1];
        float c0 = bn_b[oc0], c1 = bn_b[oc0 + 1];
        float v0[4], v1[4];
        #pragma unroll
        for (int p = 0; p < 4; p++) {
            float a0, a1; up2(accF[j][p], a0, a1);
            v0[p] = fmaxf((a0 - m0) * i0 + c0, 0.f);
            v1[p] = fmaxf((a1 - m1) * i1 + c1, 0.f);
        }
        *(float4*)&out[obase + ((size_t)oc0 * HH + gh) * WW + gwc] =
            make_float4(v0[0], v0[1], v0[2], v0[3]);
        *(float4*)&out[obase + ((size_t)(oc0 + 1) * HH + gh) * WW + gwc] =
            make_float4(v1[0], v1[1], v1[2], v1[3]);
    }
}

extern "C" void kernel_launch(void* const* d_in, const int* in_sizes, int n_in,
                              void* d_out, int out_size)
{
    const float* x  = (const float*)d_in[0];
    const float* k  = (const float*)d_in[1];
    const float* mw = (const float*)d_in[2];
    const float* mb = (const float*)d_in[3];
    const float* g  = (const float*)d_in[4];
    const float* be = (const float*)d_in[5];
    const float* mn = (const float*)d_in[6];
    const float* vr = (const float*)d_in[7];

    cudaFuncSetAttribute(hrc_kernel, cudaFuncAttributeMaxDynamicSharedMemorySize, SMEM_BYTES);

    dim3 grid(WW / TW, HH / TH, BB);   // 4 x 32 x 8 = 1024 blocks
    hrc_kernel<<<grid, NTHR, SMEM_BYTES>>>(x, k, mw, mb, g, be, mn, vr, (float*)d_out);
}

// round 13
// speedup vs baseline: 1.7908x; 1.7908x over previous
#include <cuda_runtime.h>
#include <cstdint>

// Problem constants
#define BB   8
#define CIN  64
#define COUT 64
#define RN   4
#define HH   128
#define WW   128
#define TH   4
#define TW   32
#define XROWS 6
#define XP   36
#define NTHR 256
#define KTOT 576          // CIN * 9
#define NITER 36          // 9 chunks * 4 regions

// SMEM byte offsets (W tiles 1024-aligned)
#define OFF_SX   0                    // x fp32 tile: 64*6*36*4 = 55296 B
#define OFF_W    55296                // 2 buffers x (hi 8192 + lo 8192) = 32768 B
#define OFF_SM   88064                // masks: 4*128*4 = 2048 B
#define OFF_BN   90112                // BN scale/shift: 128*4 = 512 B
#define SMEM_BYTES 90624

#define MASK_BASE ((size_t)BB*COUT*HH*WW)   // 8388608

typedef unsigned int u32;

// hi-16-bits of two fp32 -> bf16x2 (exact truncation split, hi part); f0 in low half
__device__ __forceinline__ u32 prmt7632(float a, float b) {
    u32 d; asm("prmt.b32 %0, %1, %2, 0x7632;"
               : "=r"(d) : "r"(__float_as_uint(a)), "r"(__float_as_uint(b)));
    return d;
}
// bf16x2 with v0 in low half
__device__ __forceinline__ u32 cvt_bf2(float v0, float v1) {
    u32 d; asm("cvt.rn.bf16x2.f32 %0, %1, %2;" : "=r"(d) : "f"(v1), "f"(v0)); return d;
}
__device__ __forceinline__ float truncf16(float x) {
    return __uint_as_float(__float_as_uint(x) & 0xFFFF0000u);
}
__device__ __forceinline__ u32 smem_u32(const void* p) {
    u32 a; asm("{ .reg .u64 t; cvta.to.shared.u64 t, %1; cvt.u32.u64 %0, t; }"
               : "=r"(a) : "l"(p));
    return a;
}
// warp MMA m16n8k16 bf16, fp32 accumulate in place
__device__ __forceinline__ void mma16816(float* d, const u32* a, u32 b0, u32 b1) {
    asm("mma.sync.aligned.m16n8k16.row.col.f32.bf16.bf16.f32 "
        "{%0,%1,%2,%3}, {%4,%5,%6,%7}, {%8,%9}, {%0,%1,%2,%3};"
        : "+f"(d[0]), "+f"(d[1]), "+f"(d[2]), "+f"(d[3])
        : "r"(a[0]), "r"(a[1]), "r"(a[2]), "r"(a[3]), "r"(b0), "r"(b1));
}
#define LDSM4(r0, r1, r2, r3, addr) \
    asm volatile("ldmatrix.sync.aligned.m8n8.x4.shared.b16 {%0,%1,%2,%3}, [%4];" \
                 : "=r"(r0), "=r"(r1), "=r"(r2), "=r"(r3) : "r"(addr) : "memory")

extern "C" __global__ void __launch_bounds__(NTHR, 2)
hrc_mma_kernel(const float* __restrict__ x,     const float* __restrict__ kern,
               const float* __restrict__ maskw, const float* __restrict__ maskb,
               const float* __restrict__ bn_g,  const float* __restrict__ bn_b,
               const float* __restrict__ bn_m,  const float* __restrict__ bn_v,
               float* __restrict__ out)
{
    extern __shared__ char smemc[];
    float* sxf = (float*)(smemc + OFF_SX);
    float* swm = (float*)(smemc + OFF_W);      // phase-1 scratch (mask_w + partials)
    float* smf = (float*)(smemc + OFF_SM);
    float* bnf = (float*)(smemc + OFF_BN);

    const int b   = blockIdx.z;
    const int h0  = blockIdx.y * TH;
    const int w0  = blockIdx.x * TW;
    const int tid = threadIdx.x;
    const int wid = tid >> 5;
    const int lid = tid & 31;

    // ---- load x tile (64 ch + halo), SAME zero-padding ----
    const float* xb = x + (size_t)b * CIN * HH * WW;
    for (int idx = tid; idx < CIN * XROWS * (TW + 2); idx += NTHR) {
        int ic  = idx / (XROWS * (TW + 2));
        int rem = idx - ic * (XROWS * (TW + 2));
        int r   = rem / (TW + 2);
        int c   = rem - r * (TW + 2);
        int gh = h0 - 1 + r, gw = w0 - 1 + c;
        float v = 0.f;
        if ((unsigned)gh < HH && (unsigned)gw < WW)
            v = xb[(ic * HH + gh) * WW + gw];
        sxf[(ic * XROWS + r) * XP + c] = v;
    }
    for (int idx = tid; idx < RN * CIN * 9; idx += NTHR) swm[idx] = maskw[idx];
    if (tid < COUT) {
        float s = bn_g[tid] * rsqrtf(bn_v[tid] + 1e-5f);
        bnf[tid] = s;
        bnf[64 + tid] = bn_b[tid] - bn_m[tid] * s;
    }
    __syncthreads();

    // ---- phase 1: region logits -> softmax masks ----
    {
        float* spart = swm + RN * CIN * 9;
        const int px   = tid & 127;
        const int half = tid >> 7;
        const int row = px >> 5, col = px & 31;
        float lg[RN] = {0.f, 0.f, 0.f, 0.f};
        const int ic_lo = half * (CIN / 2), ic_hi = ic_lo + CIN / 2;
        for (int ic = ic_lo; ic < ic_hi; ic++) {
            const float* xp = &sxf[(ic * XROWS + row) * XP + col];
            float xv[9];
            #pragma unroll
            for (int kh = 0; kh < 3; kh++)
                #pragma unroll
                for (int kw = 0; kw < 3; kw++) xv[kh * 3 + kw] = xp[kh * XP + kw];
            #pragma unroll
            for (int r = 0; r < RN; r++) {
                const float* wp = &swm[(r * CIN + ic) * 9];
                #pragma unroll
                for (int t = 0; t < 9; t++) lg[r] = fmaf(wp[t], xv[t], lg[r]);
            }
        }
        if (half == 1) {
            #pragma unroll
            for (int r = 0; r < RN; r++) spart[r * 128 + px] = lg[r];
        }
        __syncthreads();
        if (half == 0) {
            #pragma unroll
            for (int r = 0; r < RN; r++) lg[r] += spart[r * 128 + px] + maskb[r];
            float mx = fmaxf(fmaxf(lg[0], lg[1]), fmaxf(lg[2], lg[3]));
            float e[RN]; float s = 0.f;
            #pragma unroll
            for (int r = 0; r < RN; r++) { e[r] = expf(lg[r] - mx); s += e[r]; }
            float inv = 1.f / s;
            #pragma unroll
            for (int r = 0; r < RN; r++) {
                float m = e[r] * inv;
                smf[r * 128 + px] = m;
                out[MASK_BASE + ((size_t)(b * RN + r) * HH + (h0 + row)) * WW + (w0 + col)] = m;
            }
        }
        __syncthreads();   // smf ready; swm scratch dead -> W buffers may be written
    }

    // ---- main loop: single GEMM, K folded over (region, chunk); mask scales A ----
    // Warp w owns output rows [w*16, w*16+16), all 64 oc.
    // A fragments built directly in registers from sxf (im2col + mask scale + hi/lo split).
    // W staged per (r, chunk) as swizzled bf16 hi/lo tiles, double buffered.
    const int kq   = (lid & 3) * 2;                 // k pair base within 16
    const int px0  = wid * 16 + (lid >> 2);         // fragment row (m)
    const int xoff0 = (px0 >> 5) * XP + (px0 & 31); // sxf spatial offset (row+8 -> +8)

    // W build mapping: thread -> (oc row, k quad)
    const int ocb = tid >> 2;
    const int qq  = tid & 3;
    const u32 wxm = (u32)((ocb & 7) << 4);          // STS swizzle xor

    // ldmatrix per-lane address components
    const int rowbase = ((lid >> 4) << 3) + (lid & 7);     // 0..15
    const int q2      = (lid >> 3) & 1;
    const u32 lmxm    = (u32)((rowbase & 7) << 4);
    const u32 lmoff   = (u32)(rowbase * 128 + q2 * 16);

    const u32 wb_u32[2] = { smem_u32(smemc + OFF_W),
                            smem_u32(smemc + OFF_W + 16384) };
    char* wb_ptr[2] = { smemc + OFF_W, smemc + OFF_W + 16384 };

    const float* kb = kern + (size_t)b * RN * COUT * KTOT;

    float acc[8][4];
    #pragma unroll
    for (int n = 0; n < 8; n++)
        #pragma unroll
        for (int j = 0; j < 4; j++) acc[n][j] = 0.f;

    // prologue: stage W for iter 0 into buffer 0
    {
        const float4* gp = (const float4*)(kb + (size_t)ocb * KTOT) + (qq * 16) / 4;
        #pragma unroll
        for (int f = 0; f < 4; f++) {
            float4 v = gp[f];
            u32 o = (u32)(ocb * 128 + ((qq * 32 + f * 8) ^ wxm));
            *(uint2*)(wb_ptr[0] + o) = make_uint2(prmt7632(v.x, v.y), prmt7632(v.z, v.w));
            *(uint2*)(wb_ptr[0] + 8192 + o) = make_uint2(
                cvt_bf2(v.x - truncf16(v.x), v.y - truncf16(v.y)),
                cvt_bf2(v.z - truncf16(v.z), v.w - truncf16(v.w)));
        }
    }

    float xv[32];
    #pragma unroll 1
    for (int i = 0; i < NITER; i++) {
        const int r = i & 3, c = i >> 2;
        __syncthreads();                        // buf(i&1) visible; prior readers done

        // prefetch next W stage into registers (LDG latency overlapped with MMA)
        float4 wn[4];
        const bool hasnext = (i + 1 < NITER);
        if (hasnext) {
            const int rn = (i + 1) & 3, cn = (i + 1) >> 2;
            const float4* gp = (const float4*)(kb + ((size_t)(rn * COUT) + ocb) * KTOT)
                               + (cn * 64 + qq * 16) / 4;
            #pragma unroll
            for (int f = 0; f < 4; f++) wn[f] = gp[f];
        }

        // rebuild im2col x-values when chunk changes (shared across 4 regions)
        if (r == 0) {
            #pragma unroll
            for (int ks = 0; ks < 4; ks++) {
                #pragma unroll
                for (int e = 0; e < 4; e++) {
                    int dk = (e & 1) + ((e >> 1) << 3);      // 0,1,8,9
                    int k  = c * 64 + ks * 16 + kq + dk;
                    int ic = (k * 7282) >> 16;               // k/9 exact for k<576
                    int t  = k - ic * 9;
                    int kh = (t * 11) >> 5;                  // t/3
                    int kw = t - kh * 3;
                    int off = (ic * XROWS + kh) * XP + kw + xoff0;
                    xv[ks * 8 + e * 2 + 0] = sxf[off];
                    xv[ks * 8 + e * 2 + 1] = sxf[off + 8];   // row m+8
                }
            }
        }

        const float m0 = smf[r * 128 + px0];
        const float m1 = smf[r * 128 + px0 + 8];
        const u32 whi = wb_u32[i & 1];

        #pragma unroll
        for (int ks = 0; ks < 4; ks++) {
            const float* v8 = &xv[ks * 8];
            float s00 = m0 * v8[0], s01 = m0 * v8[2];
            float s10 = m1 * v8[1], s11 = m1 * v8[3];
            float s04 = m0 * v8[4], s05 = m0 * v8[6];
            float s14 = m1 * v8[5], s15 = m1 * v8[7];
            u32 ah[4], al[4];
            ah[0] = prmt7632(s00, s01); ah[1] = prmt7632(s10, s11);
            ah[2] = prmt7632(s04, s05); ah[3] = prmt7632(s14, s15);
            al[0] = cvt_bf2(s00 - truncf16(s00), s01 - truncf16(s01));
            al[1] = cvt_bf2(s10 - truncf16(s10), s11 - truncf16(s11));
            al[2] = cvt_bf2(s04 - truncf16(s04), s05 - truncf16(s05));
            al[3] = cvt_bf2(s14 - truncf16(s14), s15 - truncf16(s15));

            const u32 swo = (lmoff + (u32)(ks * 32)) ^ lmxm;
            #pragma unroll
            for (int ntp = 0; ntp < 4; ntp++) {
                u32 ad = whi + (u32)(ntp * 2048) + swo;
                u32 bh0, bh1, bh2, bh3, bl0, bl1, bl2, bl3;
                LDSM4(bh0, bh1, bh2, bh3, ad);
                LDSM4(bl0, bl1, bl2, bl3, ad + 8192);
                mma16816(acc[ntp * 2],     ah, bh0, bh1);   // hi*hi
                mma16816(acc[ntp * 2 + 1], ah, bh2, bh3);
                mma16816(acc[ntp * 2],     al, bh0, bh1);   // lo*hi
                mma16816(acc[ntp * 2 + 1], al, bh2, bh3);
                mma16816(acc[ntp * 2],     ah, bl0, bl1);   // hi*lo
                mma16816(acc[ntp * 2 + 1], ah, bl2, bl3);
            }
        }

        // convert + store next W stage into the other buffer
        if (hasnext) {
            char* hb = wb_ptr[(i + 1) & 1];
            #pragma unroll
            for (int f = 0; f < 4; f++) {
                float4 v = wn[f];
                u32 o = (u32)(ocb * 128 + ((qq * 32 + f * 8) ^ wxm));
                *(uint2*)(hb + o) = make_uint2(prmt7632(v.x, v.y), prmt7632(v.z, v.w));
                *(uint2*)(hb + 8192 + o) = make_uint2(
                    cvt_bf2(v.x - truncf16(v.x), v.y - truncf16(v.y)),
                    cvt_bf2(v.z - truncf16(v.z), v.w - truncf16(v.w)));
            }
        }
    }

    // ---- epilogue: BN + ReLU, scatter stores ----
    // Fragment D: c0,c1 -> (row px0, oc, oc+1); c2,c3 -> (row px0+8).
    const int prow_e = px0 >> 5;
    const int pcol_e = px0 & 31;             // px0+8 -> same prow, pcol+8
    const size_t ob = (size_t)b * COUT * HH * WW + (size_t)(h0 + prow_e) * WW + w0;
    #pragma unroll
    for (int nt = 0; nt < 8; nt++) {
        int oc = nt * 8 + (lid & 3) * 2;
        float sc0 = bnf[oc], sh0 = bnf[64 + oc];
        float sc1 = bnf[oc + 1], sh1 = bnf[64 + oc + 1];
        out[ob + (size_t)oc * (HH * WW) + pcol_e] =
            fmaxf(fmaf(acc[nt][0], sc0, sh0), 0.f);
        out[ob + (size_t)(oc + 1) * (HH * WW) + pcol_e] =
            fmaxf(fmaf(acc[nt][1], sc1, sh1), 0.f);
        out[ob + (size_t)oc * (HH * WW) + pcol_e + 8] =
            fmaxf(fmaf(acc[nt][2], sc0, sh0), 0.f);
        out[ob + (size_t)(oc + 1) * (HH * WW) + pcol_e + 8] =
            fmaxf(fmaf(acc[nt][3], sc1, sh1), 0.f);
    }
}

extern "C" void kernel_launch(void* const* d_in, const int* in_sizes, int n_in,
                              void* d_out, int out_size)
{
    const float* x  = (const float*)d_in[0];
    const float* k  = (const float*)d_in[1];
    const float* mw = (const float*)d_in[2];
    const float* mb = (const float*)d_in[3];
    const float* g  = (const float*)d_in[4];
    const float* be = (const float*)d_in[5];
    const float* mn = (const float*)d_in[6];
    const float* vr = (const float*)d_in[7];

    cudaFuncSetAttribute(hrc_mma_kernel, cudaFuncAttributeMaxDynamicSharedMemorySize,
                         SMEM_BYTES);

    dim3 grid(WW / TW, HH / TH, BB);   // 4 x 32 x 8 = 1024 blocks
    hrc_mma_kernel<<<grid, NTHR, SMEM_BYTES>>>(x, k, mw, mb, g, be, mn, vr, (float*)d_out);
}

// round 15
// speedup vs baseline: 1.7999x; 1.0050x over previous
#include <cuda_runtime.h>
#include <cstdint>

// Problem constants
#define BB   8
#define CIN  64
#define COUT 64
#define RN   4
#define HH   128
#define WW   128
#define TH   4
#define TW   32
#define XROWS 6
#define XP   36
#define NTHR 256
#define KTOT 576          // CIN * 9
#define NITER 36          // 9 chunks * 4 regions

// SMEM byte offsets (W tiles 1024-aligned)
#define OFF_SX   0                    // x fp32 tile: 64*6*36*4 = 55296 B (reused as fp32 transpose buf in epilogue)
#define OFF_W    55296                // 2 buffers x (hi 8192 + lo 8192) = 32768 B (phase1: MW tiles)
#define OFF_SM   88064                // masks: 4*128*4 = 2048 B
#define OFF_BN   90112                // BN scale/shift: 128*4 = 512 B
#define SMEM_BYTES 90624

#define MASK_BASE ((size_t)BB*COUT*HH*WW)   // 8388608
// phase-1 mask-weight tiles: hi at OFF_W + c*1024 (9 KB), lo at OFF_W + 9216 + c*1024
#define MW_LO 9216

typedef unsigned int u32;

// hi-16-bits of two fp32 -> bf16x2 (exact truncation split, hi part); f0 in low half
__device__ __forceinline__ u32 prmt7632(float a, float b) {
    u32 d; asm("prmt.b32 %0, %1, %2, 0x7632;"
               : "=r"(d) : "r"(__float_as_uint(a)), "r"(__float_as_uint(b)));
    return d;
}
// bf16x2 with v0 in low half
__device__ __forceinline__ u32 cvt_bf2(float v0, float v1) {
    u32 d; asm("cvt.rn.bf16x2.f32 %0, %1, %2;" : "=r"(d) : "f"(v1), "f"(v0)); return d;
}
__device__ __forceinline__ float truncf16(float x) {
    return __uint_as_float(__float_as_uint(x) & 0xFFFF0000u);
}
__device__ __forceinline__ u32 smem_u32(const void* p) {
    u32 a; asm("{ .reg .u64 t; cvta.to.shared.u64 t, %1; cvt.u32.u64 %0, t; }"
               : "=r"(a) : "l"(p));
    return a;
}
// warp MMA m16n8k16 bf16, fp32 accumulate in place
__device__ __forceinline__ void mma16816(float* d, const u32* a, u32 b0, u32 b1) {
    asm("mma.sync.aligned.m16n8k16.row.col.f32.bf16.bf16.f32 "
        "{%0,%1,%2,%3}, {%4,%5,%6,%7}, {%8,%9}, {%0,%1,%2,%3};"
        : "+f"(d[0]), "+f"(d[1]), "+f"(d[2]), "+f"(d[3])
        : "r"(a[0]), "r"(a[1]), "r"(a[2]), "r"(a[3]), "r"(b0), "r"(b1));
}
#define LDSM4(r0, r1, r2, r3, addr) \
    asm volatile("ldmatrix.sync.aligned.m8n8.x4.shared.b16 {%0,%1,%2,%3}, [%4];" \
                 : "=r"(r0), "=r"(r1), "=r"(r2), "=r"(r3) : "r"(addr) : "memory")
#define LDSM2(r0, r1, addr) \
    asm volatile("ldmatrix.sync.aligned.m8n8.x2.shared.b16 {%0,%1}, [%2];" \
                 : "=r"(r0), "=r"(r1) : "r"(addr) : "memory")

extern "C" __global__ void __launch_bounds__(NTHR, 2)
hrc_mma_kernel(const float* __restrict__ x,     const float* __restrict__ kern,
               const float* __restrict__ maskw, const float* __restrict__ maskb,
               const float* __restrict__ bn_g,  const float* __restrict__ bn_b,
               const float* __restrict__ bn_m,  const float* __restrict__ bn_v,
               float* __restrict__ out)
{
    extern __shared__ char smemc[];
    float* sxf = (float*)(smemc + OFF_SX);
    float* smf = (float*)(smemc + OFF_SM);
    float* bnf = (float*)(smemc + OFF_BN);

    const int b   = blockIdx.z;
    const int h0  = blockIdx.y * TH;
    const int w0  = blockIdx.x * TW;
    const int tid = threadIdx.x;
    const int wid = tid >> 5;
    const int lid = tid & 31;

    // fragment-row mapping (used by phase 1 AND the main GEMM)
    const int kq    = (lid & 3) * 2;                 // k pair base within 16
    const int px0   = wid * 16 + (lid >> 2);         // fragment row (m)
    const int xoff0 = (px0 >> 5) * XP + (px0 & 31);  // sxf spatial offset (row m+8 -> +8)

    // ---- load x tile (64 ch + halo), SAME zero-padding ----
    const float* xb = x + (size_t)b * CIN * HH * WW;
    for (int idx = tid; idx < CIN * XROWS * (TW + 2); idx += NTHR) {
        int ic  = idx / (XROWS * (TW + 2));
        int rem = idx - ic * (XROWS * (TW + 2));
        int r   = rem / (TW + 2);
        int c   = rem - r * (TW + 2);
        int gh = h0 - 1 + r, gw = w0 - 1 + c;
        float v = 0.f;
        if ((unsigned)gh < HH && (unsigned)gw < WW)
            v = xb[(ic * HH + gh) * WW + gw];
        sxf[(ic * XROWS + r) * XP + c] = v;
    }
    // zero MW tile area (rows 4-7 of each 8-row tile must be 0)
    for (int i = tid; i < 4608; i += NTHR) ((u32*)(smemc + OFF_W))[i] = 0;
    if (tid < COUT) {
        float s = bn_g[tid] * rsqrtf(bn_v[tid] + 1e-5f);
        bnf[tid] = s;
        bnf[64 + tid] = bn_b[tid] - bn_m[tid] * s;
    }
    __syncthreads();

    // ---- build mask-weight hi/lo tiles: 9 chunks, 8 rows (4 real + 4 zero) x 128 B, swizzled ----
    for (int idx = tid; idx < RN * KTOT; idx += NTHR) {
        int r = idx / KTOT, k = idx - r * KTOT;
        int c = k >> 6, kk = k & 63;
        float v = maskw[idx];
        u32 off = (u32)(c * 1024 + ((r * 128 + kk * 2) ^ (r << 4)));
        *(unsigned short*)(smemc + OFF_W + off) =
            (unsigned short)(__float_as_uint(v) >> 16);
        float vl = v - truncf16(v);
        *(unsigned short*)(smemc + OFF_W + MW_LO + off) =
            (unsigned short)(cvt_bf2(vl, vl) & 0xFFFFu);
    }
    __syncthreads();

    // ---- phase 1: region logits via MMA (same im2col, N=8 tile) -> softmax masks ----
    {
        float lg[4] = {0.f, 0.f, 0.f, 0.f};
        const u32 mwbase = smem_u32(smemc + OFF_W);
        const int rw = lid & 7, hf = (lid >> 3) & 1;
        float xv[32];
        #pragma unroll 1
        for (int c = 0; c < 9; c++) {
            #pragma unroll
            for (int ks = 0; ks < 4; ks++) {
                #pragma unroll
                for (int e = 0; e < 4; e++) {
                    int dk = (e & 1) + ((e >> 1) << 3);      // 0,1,8,9
                    int k  = c * 64 + ks * 16 + kq + dk;
                    int ic = (k * 7282) >> 16;               // k/9 exact for k<576
                    int t  = k - ic * 9;
                    int kh = (t * 11) >> 5;                  // t/3
                    int kw = t - kh * 3;
                    int off = (ic * XROWS + kh) * XP + kw + xoff0;
                    xv[ks * 8 + e * 2 + 0] = sxf[off];
                    xv[ks * 8 + e * 2 + 1] = sxf[off + 8];
                }
            }
            #pragma unroll
            for (int ks = 0; ks < 4; ks++) {
                const float* v8 = &xv[ks * 8];
                u32 ah[4], al[4];
                ah[0] = prmt7632(v8[0], v8[2]); ah[1] = prmt7632(v8[1], v8[3]);
                ah[2] = prmt7632(v8[4], v8[6]); ah[3] = prmt7632(v8[5], v8[7]);
                al[0] = cvt_bf2(v8[0] - truncf16(v8[0]), v8[2] - truncf16(v8[2]));
                al[1] = cvt_bf2(v8[1] - truncf16(v8[1]), v8[3] - truncf16(v8[3]));
                al[2] = cvt_bf2(v8[4] - truncf16(v8[4]), v8[6] - truncf16(v8[6]));
                al[3] = cvt_bf2(v8[5] - truncf16(v8[5]), v8[7] - truncf16(v8[7]));
                u32 lmo = (u32)((rw * 128 + ks * 32 + hf * 16) ^ (rw << 4)) + (u32)(c * 1024);
                u32 bh0, bh1, bl0, bl1;
                LDSM2(bh0, bh1, mwbase + lmo);
                LDSM2(bl0, bl1, mwbase + MW_LO + lmo);
                mma16816(lg, ah, bh0, bh1);   // hi*hi
                mma16816(lg, al, bh0, bh1);   // lo*hi
                mma16816(lg, ah, bl0, bl1);   // hi*lo
            }
        }
        // gather 4 region logits per row via quad exchange, softmax, write
        float p0 = __shfl_xor_sync(0xffffffffu, lg[0], 1);
        float p1 = __shfl_xor_sync(0xffffffffu, lg[1], 1);
        float p2 = __shfl_xor_sync(0xffffffffu, lg[2], 1);
        float p3 = __shfl_xor_sync(0xffffffffu, lg[3], 1);
        int q = lid & 3;
        if (q < 2) {
            float l0, l1, l2, l3; int px;
            if (q == 0) { l0 = lg[0]; l1 = lg[1]; l2 = p0; l3 = p1; px = px0; }
            else        { l0 = p2; l1 = p3; l2 = lg[2]; l3 = lg[3]; px = px0 + 8; }
            l0 += maskb[0]; l1 += maskb[1]; l2 += maskb[2]; l3 += maskb[3];
            float mx = fmaxf(fmaxf(l0, l1), fmaxf(l2, l3));
            float e0 = expf(l0 - mx), e1 = expf(l1 - mx);
            float e2 = expf(l2 - mx), e3 = expf(l3 - mx);
            float inv = 1.f / (e0 + e1 + e2 + e3);
            float m[4] = {e0 * inv, e1 * inv, e2 * inv, e3 * inv};
            int prow = px >> 5, pcol = px & 31;
            #pragma unroll
            for (int r = 0; r < RN; r++) {
                smf[r * 128 + px] = m[r];
                out[MASK_BASE + ((size_t)(b * RN + r) * HH + h0 + prow) * WW + w0 + pcol] = m[r];
            }
        }
        __syncthreads();   // smf ready; MW tiles dead -> W buffers may be written
    }

    // ---- main loop: single GEMM, K folded over (region, chunk); mask scales A ----
    const int ocb = tid >> 2;
    const int qq  = tid & 3;
    const u32 wxm = (u32)((ocb & 7) << 4);

    const int rowbase = ((lid >> 4) << 3) + (lid & 7);     // 0..15
    const int q2      = (lid >> 3) & 1;
    const u32 lmxm    = (u32)((rowbase & 7) << 4);
    const u32 lmoff   = (u32)(rowbase * 128 + q2 * 16);

    const u32 wb_u32[2] = { smem_u32(smemc + OFF_W),
                            smem_u32(smemc + OFF_W + 16384) };
    char* wb_ptr[2] = { smemc + OFF_W, smemc + OFF_W + 16384 };

    const float* kb = kern + (size_t)b * RN * COUT * KTOT;

    float acc[8][4];
    #pragma unroll
    for (int n = 0; n < 8; n++)
        #pragma unroll
        for (int j = 0; j < 4; j++) acc[n][j] = 0.f;

    // prologue: stage W for iter 0 into buffer 0
    {
        const float4* gp = (const float4*)(kb + (size_t)ocb * KTOT) + (qq * 16) / 4;
        #pragma unroll
        for (int f = 0; f < 4; f++) {
            float4 v = gp[f];
            u32 o = (u32)(ocb * 128 + ((qq * 32 + f * 8) ^ wxm));
            *(uint2*)(wb_ptr[0] + o) = make_uint2(prmt7632(v.x, v.y), prmt7632(v.z, v.w));
            *(uint2*)(wb_ptr[0] + 8192 + o) = make_uint2(
                cvt_bf2(v.x - truncf16(v.x), v.y - truncf16(v.y)),
                cvt_bf2(v.z - truncf16(v.z), v.w - truncf16(v.w)));
        }
    }

    float xv[32];
    #pragma unroll 1
    for (int i = 0; i < NITER; i++) {
        const int r = i & 3, c = i >> 2;
        __syncthreads();                        // buf(i&1) visible; prior readers done

        // prefetch next W stage into registers (LDG latency overlapped with MMA)
        float4 wn[4];
        const bool hasnext = (i + 1 < NITER);
        if (hasnext) {
            const int rn = (i + 1) & 3, cn = (i + 1) >> 2;
            const float4* gp = (const float4*)(kb + ((size_t)(rn * COUT) + ocb) * KTOT)
                               + (cn * 64 + qq * 16) / 4;
            #pragma unroll
            for (int f = 0; f < 4; f++) wn[f] = gp[f];
        }

        // rebuild im2col x-values when chunk changes (shared across 4 regions)
        if (r == 0) {
            #pragma unroll
            for (int ks = 0; ks < 4; ks++) {
                #pragma unroll
                for (int e = 0; e < 4; e++) {
                    int dk = (e & 1) + ((e >> 1) << 3);      // 0,1,8,9
                    int k  = c * 64 + ks * 16 + kq + dk;
                    int ic = (k * 7282) >> 16;               // k/9 exact for k<576
                    int t  = k - ic * 9;
                    int kh = (t * 11) >> 5;                  // t/3
                    int kw = t - kh * 3;
                    int off = (ic * XROWS + kh) * XP + kw + xoff0;
                    xv[ks * 8 + e * 2 + 0] = sxf[off];
                    xv[ks * 8 + e * 2 + 1] = sxf[off + 8];   // row m+8
                }
            }
        }

        const float m0 = smf[r * 128 + px0];
        const float m1 = smf[r * 128 + px0 + 8];
        const u32 whi = wb_u32[i & 1];

        #pragma unroll
        for (int ks = 0; ks < 4; ks++) {
            const float* v8 = &xv[ks * 8];
            float s00 = m0 * v8[0], s01 = m0 * v8[2];
            float s10 = m1 * v8[1], s11 = m1 * v8[3];
            float s04 = m0 * v8[4], s05 = m0 * v8[6];
            float s14 = m1 * v8[5], s15 = m1 * v8[7];
            u32 ah[4], al[4];
            ah[0] = prmt7632(s00, s01); ah[1] = prmt7632(s10, s11);
            ah[2] = prmt7632(s04, s05); ah[3] = prmt7632(s14, s15);
            al[0] = cvt_bf2(s00 - truncf16(s00), s01 - truncf16(s01));
            al[1] = cvt_bf2(s10 - truncf16(s10), s11 - truncf16(s11));
            al[2] = cvt_bf2(s04 - truncf16(s04), s05 - truncf16(s05));
            al[3] = cvt_bf2(s14 - truncf16(s14), s15 - truncf16(s15));

            const u32 swo = (lmoff + (u32)(ks * 32)) ^ lmxm;
            #pragma unroll
            for (int ntp = 0; ntp < 4; ntp++) {
                u32 ad = whi + (u32)(ntp * 2048) + swo;
                u32 bh0, bh1, bh2, bh3, bl0, bl1, bl2, bl3;
                LDSM4(bh0, bh1, bh2, bh3, ad);
                LDSM4(bl0, bl1, bl2, bl3, ad + 8192);
                mma16816(acc[ntp * 2],     ah, bh0, bh1);   // hi*hi
                mma16816(acc[ntp * 2 + 1], ah, bh2, bh3);
                mma16816(acc[ntp * 2],     al, bh0, bh1);   // lo*hi
                mma16816(acc[ntp * 2 + 1], al, bh2, bh3);
                mma16816(acc[ntp * 2],     ah, bl0, bl1);   // hi*lo
                mma16816(acc[ntp * 2 + 1], ah, bl2, bl3);
            }
        }

        // convert + store next W stage into the other buffer
        if (hasnext) {
            char* hb = wb_ptr[(i + 1) & 1];
            #pragma unroll
            for (int f = 0; f < 4; f++) {
                float4 v = wn[f];
                u32 o = (u32)(ocb * 128 + ((qq * 32 + f * 8) ^ wxm));
                *(uint2*)(hb + o) = make_uint2(prmt7632(v.x, v.y), prmt7632(v.z, v.w));
                *(uint2*)(hb + 8192 + o) = make_uint2(
                    cvt_bf2(v.x - truncf16(v.x), v.y - truncf16(v.y)),
                    cvt_bf2(v.z - truncf16(v.z), v.w - truncf16(v.w)));
            }
        }
    }

    // ---- epilogue: transpose through smem (reuse sx), BN + ReLU, coalesced stores ----
    // S[px][oc], pitch 67 (near conflict-free for both phases)
    float* S = sxf;
    #pragma unroll
    for (int nt = 0; nt < 8; nt++) {
        int col = nt * 8 + (lid & 3) * 2;
        S[px0 * 67 + col]           = acc[nt][0];
        S[px0 * 67 + col + 1]       = acc[nt][1];
        S[(px0 + 8) * 67 + col]     = acc[nt][2];
        S[(px0 + 8) * 67 + col + 1] = acc[nt][3];
    }
    __syncthreads();
    const size_t ob = (size_t)b * COUT * HH * WW;
    const int lanepos = tid & 7;
    #pragma unroll
    for (int i = 0; i < 8; i++) {
        int line = (tid >> 3) + 32 * i;          // 0..255
        int oc = line & 63, prow = line >> 6;
        float sc = bnf[oc], sh = bnf[64 + oc];
        int rb = prow * 32 + lanepos * 4;
        float4 v;
        v.x = fmaxf(fmaf(S[(rb + 0) * 67 + oc], sc, sh), 0.f);
        v.y = fmaxf(fmaf(S[(rb + 1) * 67 + oc], sc, sh), 0.f);
        v.z = fmaxf(fmaf(S[(rb + 2) * 67 + oc], sc, sh), 0.f);
        v.w = fmaxf(fmaf(S[(rb + 3) * 67 + oc], sc, sh), 0.f);
        *(float4*)&out[ob + (size_t)oc * (HH * WW) + (size_t)(h0 + prow) * WW
                       + w0 + lanepos * 4] = v;
    }
}

extern "C" void kernel_launch(void* const* d_in, const int* in_sizes, int n_in,
                              void* d_out, int out_size)
{
    const float* x  = (const float*)d_in[0];
    const float* k  = (const float*)d_in[1];
    const float* mw = (const float*)d_in[2];
    const float* mb = (const float*)d_in[3];
    const float* g  = (const float*)d_in[4];
    const float* be = (const float*)d_in[5];
    const float* mn = (const float*)d_in[6];
    const float* vr = (const float*)d_in[7];

    cudaFuncSetAttribute(hrc_mma_kernel, cudaFuncAttributeMaxDynamicSharedMemorySize,
                         SMEM_BYTES);

    dim3 grid(WW / TW, HH / TH, BB);   // 4 x 32 x 8 = 1024 blocks
    hrc_mma_kernel<<<grid, NTHR, SMEM_BYTES>>>(x, k, mw, mb, g, be, mn, vr, (float*)d_out);
}

// round 16
// speedup vs baseline: 1.8093x; 1.0052x over previous
#include <cuda_runtime.h>
#include <cstdint>

// Problem constants
#define BB   8
#define CIN  64
#define COUT 64
#define RN   4
#define HH   128
#define WW   128
#define TH   4
#define TW   32
#define XROWS 6
#define XP   36
#define NTHR 256
#define KTOT 576          // CIN * 9
#define NITER 36          // 9 chunks * 4 regions (region fastest)

// SMEM byte offsets (W tiles 1024-aligned)
#define OFF_SX   0                    // x fp32 tile: 64*6*36*4 = 55296 B (reused as transpose buf)
#define OFF_W    55296                // 2 buffers x (hi 8192 + lo 8192) = 32768 B (phase1: MW tiles)
#define OFF_SM   88064                // masks: 4*128*4 = 2048 B
#define OFF_BN   90112                // BN scale/shift: 128*4 = 512 B
#define SMEM_BYTES 90624

#define MASK_BASE ((size_t)BB*COUT*HH*WW)   // 8388608
#define MW_LO 9216

typedef unsigned int u32;

// hi-16-bits of two fp32 -> bf16x2 (exact truncation split, hi part); f0 in low half
__device__ __forceinline__ u32 prmt7632(float a, float b) {
    u32 d; asm("prmt.b32 %0, %1, %2, 0x7632;"
               : "=r"(d) : "r"(__float_as_uint(a)), "r"(__float_as_uint(b)));
    return d;
}
// bf16x2 with v0 in low half
__device__ __forceinline__ u32 cvt_bf2(float v0, float v1) {
    u32 d; asm("cvt.rn.bf16x2.f32 %0, %1, %2;" : "=r"(d) : "f"(v1), "f"(v0)); return d;
}
__device__ __forceinline__ float truncf16(float x) {
    return __uint_as_float(__float_as_uint(x) & 0xFFFF0000u);
}
__device__ __forceinline__ u32 smem_u32(const void* p) {
    u32 a; asm("{ .reg .u64 t; cvta.to.shared.u64 t, %1; cvt.u32.u64 %0, t; }"
               : "=r"(a) : "l"(p));
    return a;
}
// warp MMA m16n8k16 bf16, fp32 accumulate in place
__device__ __forceinline__ void mma16816(float* d, const u32* a, u32 b0, u32 b1) {
    asm("mma.sync.aligned.m16n8k16.row.col.f32.bf16.bf16.f32 "
        "{%0,%1,%2,%3}, {%4,%5,%6,%7}, {%8,%9}, {%0,%1,%2,%3};"
        : "+f"(d[0]), "+f"(d[1]), "+f"(d[2]), "+f"(d[3])
        : "r"(a[0]), "r"(a[1]), "r"(a[2]), "r"(a[3]), "r"(b0), "r"(b1));
}
#define LDSM4(r0, r1, r2, r3, addr) \
    asm volatile("ldmatrix.sync.aligned.m8n8.x4.shared.b16 {%0,%1,%2,%3}, [%4];" \
                 : "=r"(r0), "=r"(r1), "=r"(r2), "=r"(r3) : "r"(addr) : "memory")
#define LDSM2(r0, r1, addr) \
    asm volatile("ldmatrix.sync.aligned.m8n8.x2.shared.b16 {%0,%1}, [%2];" \
                 : "=r"(r0), "=r"(r1) : "r"(addr) : "memory")

extern "C" __global__ void __launch_bounds__(NTHR, 2)
hrc_mma_kernel(const float* __restrict__ x,     const float* __restrict__ kern,
               const float* __restrict__ maskw, const float* __restrict__ maskb,
               const float* __restrict__ bn_g,  const float* __restrict__ bn_b,
               const float* __restrict__ bn_m,  const float* __restrict__ bn_v,
               float* __restrict__ out)
{
    extern __shared__ char smemc[];
    float* sxf = (float*)(smemc + OFF_SX);
    float* smf = (float*)(smemc + OFF_SM);
    float* bnf = (float*)(smemc + OFF_BN);

    const int b   = blockIdx.z;
    const int h0  = blockIdx.y * TH;
    const int w0  = blockIdx.x * TW;
    const int tid = threadIdx.x;
    const int wid = tid >> 5;
    const int lid = tid & 31;

    // fragment-row mapping (phase 1 AND main GEMM)
    const int kq    = (lid & 3) * 2;
    const int px0   = wid * 16 + (lid >> 2);
    const int xoff0 = (px0 >> 5) * XP + (px0 & 31);

    // ---- load x tile (64 ch + halo), SAME zero-padding ----
    const float* xb = x + (size_t)b * CIN * HH * WW;
    for (int idx = tid; idx < CIN * XROWS * (TW + 2); idx += NTHR) {
        int ic  = idx / (XROWS * (TW + 2));
        int rem = idx - ic * (XROWS * (TW + 2));
        int r   = rem / (TW + 2);
        int c   = rem - r * (TW + 2);
        int gh = h0 - 1 + r, gw = w0 - 1 + c;
        float v = 0.f;
        if ((unsigned)gh < HH && (unsigned)gw < WW)
            v = xb[(ic * HH + gh) * WW + gw];
        sxf[(ic * XROWS + r) * XP + c] = v;
    }
    // zero MW tile area (rows 4-7 of each 8-row tile must be 0)
    for (int i = tid; i < 4608; i += NTHR) ((u32*)(smemc + OFF_W))[i] = 0;
    if (tid < COUT) {
        float s = bn_g[tid] * rsqrtf(bn_v[tid] + 1e-5f);
        bnf[tid] = s;
        bnf[64 + tid] = bn_b[tid] - bn_m[tid] * s;
    }
    __syncthreads();

    // ---- build mask-weight hi/lo tiles: 9 chunks, 8 rows (4 real + 4 zero) x 128 B ----
    for (int idx = tid; idx < RN * KTOT; idx += NTHR) {
        int r = idx / KTOT, k = idx - r * KTOT;
        int c = k >> 6, kk = k & 63;
        float v = maskw[idx];
        u32 off = (u32)(c * 1024 + ((r * 128 + kk * 2) ^ (r << 4)));
        *(unsigned short*)(smemc + OFF_W + off) =
            (unsigned short)(__float_as_uint(v) >> 16);
        float vl = v - truncf16(v);
        *(unsigned short*)(smemc + OFF_W + MW_LO + off) =
            (unsigned short)(cvt_bf2(vl, vl) & 0xFFFFu);
    }
    __syncthreads();

    // ---- phase 1: region logits via MMA -> softmax masks ----
    {
        float lg[4] = {0.f, 0.f, 0.f, 0.f};
        const u32 mwbase = smem_u32(smemc + OFF_W);
        const int rw = lid & 7, hf = (lid >> 3) & 1;
        float xv[32];
        #pragma unroll 1
        for (int c = 0; c < 9; c++) {
            #pragma unroll
            for (int ks = 0; ks < 4; ks++) {
                #pragma unroll
                for (int e = 0; e < 4; e++) {
                    int dk = (e & 1) + ((e >> 1) << 3);
                    int k  = c * 64 + ks * 16 + kq + dk;
                    int ic = (k * 7282) >> 16;
                    int t  = k - ic * 9;
                    int kh = (t * 11) >> 5;
                    int kw = t - kh * 3;
                    int off = (ic * XROWS + kh) * XP + kw + xoff0;
                    xv[ks * 8 + e * 2 + 0] = sxf[off];
                    xv[ks * 8 + e * 2 + 1] = sxf[off + 8];
                }
            }
            #pragma unroll
            for (int ks = 0; ks < 4; ks++) {
                const float* v8 = &xv[ks * 8];
                u32 ah[4], al[4];
                ah[0] = prmt7632(v8[0], v8[2]); ah[1] = prmt7632(v8[1], v8[3]);
                ah[2] = prmt7632(v8[4], v8[6]); ah[3] = prmt7632(v8[5], v8[7]);
                al[0] = cvt_bf2(v8[0] - truncf16(v8[0]), v8[2] - truncf16(v8[2]));
                al[1] = cvt_bf2(v8[1] - truncf16(v8[1]), v8[3] - truncf16(v8[3]));
                al[2] = cvt_bf2(v8[4] - truncf16(v8[4]), v8[6] - truncf16(v8[6]));
                al[3] = cvt_bf2(v8[5] - truncf16(v8[5]), v8[7] - truncf16(v8[7]));
                u32 lmo = (u32)((rw * 128 + ks * 32 + hf * 16) ^ (rw << 4)) + (u32)(c * 1024);
                u32 bh0, bh1, bl0, bl1;
                LDSM2(bh0, bh1, mwbase + lmo);
                LDSM2(bl0, bl1, mwbase + MW_LO + lmo);
                mma16816(lg, ah, bh0, bh1);   // hi*hi
                mma16816(lg, al, bh0, bh1);   // lo*hi
                mma16816(lg, ah, bl0, bl1);   // hi*lo
            }
        }
        float p0 = __shfl_xor_sync(0xffffffffu, lg[0], 1);
        float p1 = __shfl_xor_sync(0xffffffffu, lg[1], 1);
        float p2 = __shfl_xor_sync(0xffffffffu, lg[2], 1);
        float p3 = __shfl_xor_sync(0xffffffffu, lg[3], 1);
        int q = lid & 3;
        if (q < 2) {
            float l0, l1, l2, l3; int px;
            if (q == 0) { l0 = lg[0]; l1 = lg[1]; l2 = p0; l3 = p1; px = px0; }
            else        { l0 = p2; l1 = p3; l2 = lg[2]; l3 = lg[3]; px = px0 + 8; }
            l0 += maskb[0]; l1 += maskb[1]; l2 += maskb[2]; l3 += maskb[3];
            float mx = fmaxf(fmaxf(l0, l1), fmaxf(l2, l3));
            float e0 = expf(l0 - mx), e1 = expf(l1 - mx);
            float e2 = expf(l2 - mx), e3 = expf(l3 - mx);
            float inv = 1.f / (e0 + e1 + e2 + e3);
            float m[4] = {e0 * inv, e1 * inv, e2 * inv, e3 * inv};
            int prow = px >> 5, pcol = px & 31;
            #pragma unroll
            for (int r = 0; r < RN; r++) {
                smf[r * 128 + px] = m[r];
                out[MASK_BASE + ((size_t)(b * RN + r) * HH + h0 + prow) * WW + w0 + pcol] = m[r];
            }
        }
        __syncthreads();   // smf ready; MW tiles dead -> W buffers may be written
    }

    // ---- main loop: unscaled A split once per chunk; per-region tmp accum + mask fold ----
    const int ocb = tid >> 2;
    const int qq  = tid & 3;
    const u32 wxm = (u32)((ocb & 7) << 4);

    const int rowbase = ((lid >> 4) << 3) + (lid & 7);
    const int q2      = (lid >> 3) & 1;
    const u32 lmxm    = (u32)((rowbase & 7) << 4);
    const u32 lmoff   = (u32)(rowbase * 128 + q2 * 16);

    const u32 wb_u32[2] = { smem_u32(smemc + OFF_W),
                            smem_u32(smemc + OFF_W + 16384) };
    char* wb_ptr[2] = { smemc + OFF_W, smemc + OFF_W + 16384 };

    const float* kb = kern + (size_t)b * RN * COUT * KTOT;

    float acc[8][4];
    #pragma unroll
    for (int n = 0; n < 8; n++)
        #pragma unroll
        for (int j = 0; j < 4; j++) acc[n][j] = 0.f;

    // prologue: stage W for iter 0 into buffer 0
    {
        const float4* gp = (const float4*)(kb + (size_t)ocb * KTOT) + (qq * 16) / 4;
        #pragma unroll
        for (int f = 0; f < 4; f++) {
            float4 v = gp[f];
            u32 o = (u32)(ocb * 128 + ((qq * 32 + f * 8) ^ wxm));
            *(uint2*)(wb_ptr[0] + o) = make_uint2(prmt7632(v.x, v.y), prmt7632(v.z, v.w));
            *(uint2*)(wb_ptr[0] + 8192 + o) = make_uint2(
                cvt_bf2(v.x - truncf16(v.x), v.y - truncf16(v.y)),
                cvt_bf2(v.z - truncf16(v.z), v.w - truncf16(v.w)));
        }
    }

    u32 ah[16], al[16];   // A fragments for 4 k-steps (unscaled, region-independent)
    #pragma unroll 1
    for (int i = 0; i < NITER; i++) {
        const int r = i & 3, c = i >> 2;
        __syncthreads();                        // buf(i&1) visible; prior readers done

        // prefetch next W stage into registers (LDG latency overlapped with MMA)
        float4 wn[4];
        const bool hasnext = (i + 1 < NITER);
        if (hasnext) {
            const int rn = (i + 1) & 3, cn = (i + 1) >> 2;
            const float4* gp = (const float4*)(kb + ((size_t)(rn * COUT) + ocb) * KTOT)
                               + (cn * 64 + qq * 16) / 4;
            #pragma unroll
            for (int f = 0; f < 4; f++) wn[f] = gp[f];
        }

        // rebuild A fragments when chunk changes (shared across all 4 regions)
        if (r == 0) {
            #pragma unroll
            for (int ks = 0; ks < 4; ks++) {
                float v8[8];
                #pragma unroll
                for (int e = 0; e < 4; e++) {
                    int dk = (e & 1) + ((e >> 1) << 3);      // 0,1,8,9
                    int k  = c * 64 + ks * 16 + kq + dk;
                    int ic = (k * 7282) >> 16;               // k/9 exact for k<576
                    int t  = k - ic * 9;
                    int kh = (t * 11) >> 5;                  // t/3
                    int kw = t - kh * 3;
                    int off = (ic * XROWS + kh) * XP + kw + xoff0;
                    v8[e * 2 + 0] = sxf[off];
                    v8[e * 2 + 1] = sxf[off + 8];            // row m+8
                }
                ah[ks * 4 + 0] = prmt7632(v8[0], v8[2]);
                ah[ks * 4 + 1] = prmt7632(v8[1], v8[3]);
                ah[ks * 4 + 2] = prmt7632(v8[4], v8[6]);
                ah[ks * 4 + 3] = prmt7632(v8[5], v8[7]);
                al[ks * 4 + 0] = cvt_bf2(v8[0] - truncf16(v8[0]), v8[2] - truncf16(v8[2]));
                al[ks * 4 + 1] = cvt_bf2(v8[1] - truncf16(v8[1]), v8[3] - truncf16(v8[3]));
                al[ks * 4 + 2] = cvt_bf2(v8[4] - truncf16(v8[4]), v8[6] - truncf16(v8[6]));
                al[ks * 4 + 3] = cvt_bf2(v8[5] - truncf16(v8[5]), v8[7] - truncf16(v8[7]));
            }
        }

        const float m0 = smf[r * 128 + px0];
        const float m1 = smf[r * 128 + px0 + 8];
        const u32 whi = wb_u32[i & 1];

        // per n-tile pair: accumulate this (region, chunk) slice in tmp, then mask-fold
        #pragma unroll
        for (int ntp = 0; ntp < 4; ntp++) {
            float t0[4] = {0.f, 0.f, 0.f, 0.f};
            float t1[4] = {0.f, 0.f, 0.f, 0.f};
            #pragma unroll
            for (int ks = 0; ks < 4; ks++) {
                u32 ad = whi + (u32)(ntp * 2048) + (((lmoff + (u32)(ks * 32))) ^ lmxm);
                u32 bh0, bh1, bh2, bh3, bl0, bl1, bl2, bl3;
                LDSM4(bh0, bh1, bh2, bh3, ad);
                LDSM4(bl0, bl1, bl2, bl3, ad + 8192);
                const u32* ahk = &ah[ks * 4];
                const u32* alk = &al[ks * 4];
                mma16816(t0, ahk, bh0, bh1);   // hi*hi
                mma16816(t1, ahk, bh2, bh3);
                mma16816(t0, alk, bh0, bh1);   // lo*hi
                mma16816(t1, alk, bh2, bh3);
                mma16816(t0, ahk, bl0, bl1);   // hi*lo
                mma16816(t1, ahk, bl2, bl3);
            }
            acc[ntp * 2][0]     = fmaf(m0, t0[0], acc[ntp * 2][0]);
            acc[ntp * 2][1]     = fmaf(m0, t0[1], acc[ntp * 2][1]);
            acc[ntp * 2][2]     = fmaf(m1, t0[2], acc[ntp * 2][2]);
            acc[ntp * 2][3]     = fmaf(m1, t0[3], acc[ntp * 2][3]);
            acc[ntp * 2 + 1][0] = fmaf(m0, t1[0], acc[ntp * 2 + 1][0]);
            acc[ntp * 2 + 1][1] = fmaf(m0, t1[1], acc[ntp * 2 + 1][1]);
            acc[ntp * 2 + 1][2] = fmaf(m1, t1[2], acc[ntp * 2 + 1][2]);
            acc[ntp * 2 + 1][3] = fmaf(m1, t1[3], acc[ntp * 2 + 1][3]);
        }

        // convert + store next W stage into the other buffer
        if (hasnext) {
            char* hb = wb_ptr[(i + 1) & 1];
            #pragma unroll
            for (int f = 0; f < 4; f++) {
                float4 v = wn[f];
                u32 o = (u32)(ocb * 128 + ((qq * 32 + f * 8) ^ wxm));
                *(uint2*)(hb + o) = make_uint2(prmt7632(v.x, v.y), prmt7632(v.z, v.w));
                *(uint2*)(hb + 8192 + o) = make_uint2(
                    cvt_bf2(v.x - truncf16(v.x), v.y - truncf16(v.y)),
                    cvt_bf2(v.z - truncf16(v.z), v.w - truncf16(v.w)));
            }
        }
    }

    // ---- epilogue: transpose through smem (reuse sx), BN + ReLU, coalesced stores ----
    float* S = sxf;
    #pragma unroll
    for (int nt = 0; nt < 8; nt++) {
        int col = nt * 8 + (lid & 3) * 2;
        S[px0 * 67 + col]           = acc[nt][0];
        S[px0 * 67 + col + 1]       = acc[nt][1];
        S[(px0 + 8) * 67 + col]     = acc[nt][2];
        S[(px0 + 8) * 67 + col + 1] = acc[nt][3];
    }
    __syncthreads();
    const size_t ob = (size_t)b * COUT * HH * WW;
    const int lanepos = tid & 7;
    #pragma unroll
    for (int i = 0; i < 8; i++) {
        int line = (tid >> 3) + 32 * i;          // 0..255
        int oc = line & 63, prow = line >> 6;
        float sc = bnf[oc], sh = bnf[64 + oc];
        int rb = prow * 32 + lanepos * 4;
        float4 v;
        v.x = fmaxf(fmaf(S[(rb + 0) * 67 + oc], sc, sh), 0.f);
        v.y = fmaxf(fmaf(S[(rb + 1) * 67 + oc], sc, sh), 0.f);
        v.z = fmaxf(fmaf(S[(rb + 2) * 67 + oc], sc, sh), 0.f);
        v.w = fmaxf(fmaf(S[(rb + 3) * 67 + oc], sc, sh), 0.f);
        *(float4*)&out[ob + (size_t)oc * (HH * WW) + (size_t)(h0 + prow) * WW
                       + w0 + lanepos * 4] = v;
    }
}

extern "C" void kernel_launch(void* const* d_in, const int* in_sizes, int n_in,
                              void* d_out, int out_size)
{
    const float* x  = (const float*)d_in[0];
    const float* k  = (const float*)d_in[1];
    const float* mw = (const float*)d_in[2];
    const float* mb = (const float*)d_in[3];
    const float* g  = (const float*)d_in[4];
    const float* be = (const float*)d_in[5];
    const float* mn = (const float*)d_in[6];
    const float* vr = (const float*)d_in[7];

    cudaFuncSetAttribute(hrc_mma_kernel, cudaFuncAttributeMaxDynamicSharedMemorySize,
                         SMEM_BYTES);

    dim3 grid(WW / TW, HH / TH, BB);   // 4 x 32 x 8 = 1024 blocks
    hrc_mma_kernel<<<grid, NTHR, SMEM_BYTES>>>(x, k, mw, mb, g, be, mn, vr, (float*)d_out);
}

// round 17
// speedup vs baseline: 1.8570x; 1.0264x over previous
#include <cuda_runtime.h>
#include <cstdint>

// Problem constants
#define BB   8
#define CIN  64
#define COUT 64
#define RN   4
#define HH   128
#define WW   128
#define TH   4
#define TW   32
#define XROWS 6
#define XP   36
#define NTHR 256
#define KTOT 576          // CIN * 9
#define NITER 36          // 9 chunks * 4 regions (region fastest)

// SMEM byte offsets (W tiles 1024-aligned)
#define OFF_SX   0                    // x fp32 tile: 64*6*36*4 = 55296 B (reused as transpose buf)
#define OFF_W    55296                // 2 buffers x (hi 8192 + lo 8192) = 32768 B (phase1: MW tiles)
#define OFF_SM   88064                // masks: 4*128*4 = 2048 B
#define OFF_BN   90112                // BN scale/shift: 128*4 = 512 B
#define SMEM_BYTES 90624

#define MASK_BASE ((size_t)BB*COUT*HH*WW)   // 8388608
#define MW_LO 9216

typedef unsigned int u32;

// hi-16-bits of two fp32 -> bf16x2 (exact truncation split, hi part); f0 in low half
__device__ __forceinline__ u32 prmt7632(float a, float b) {
    u32 d; asm("prmt.b32 %0, %1, %2, 0x7632;"
               : "=r"(d) : "r"(__float_as_uint(a)), "r"(__float_as_uint(b)));
    return d;
}
// bf16x2 with v0 in low half
__device__ __forceinline__ u32 cvt_bf2(float v0, float v1) {
    u32 d; asm("cvt.rn.bf16x2.f32 %0, %1, %2;" : "=r"(d) : "f"(v1), "f"(v0)); return d;
}
__device__ __forceinline__ float truncf16(float x) {
    return __uint_as_float(__float_as_uint(x) & 0xFFFF0000u);
}
__device__ __forceinline__ u32 smem_u32(const void* p) {
    u32 a; asm("{ .reg .u64 t; cvta.to.shared.u64 t, %1; cvt.u32.u64 %0, t; }"
               : "=r"(a) : "l"(p));
    return a;
}
// warp MMA m16n8k16 bf16, fp32 accumulate in place
__device__ __forceinline__ void mma16816(float* d, const u32* a, u32 b0, u32 b1) {
    asm("mma.sync.aligned.m16n8k16.row.col.f32.bf16.bf16.f32 "
        "{%0,%1,%2,%3}, {%4,%5,%6,%7}, {%8,%9}, {%0,%1,%2,%3};"
        : "+f"(d[0]), "+f"(d[1]), "+f"(d[2]), "+f"(d[3])
        : "r"(a[0]), "r"(a[1]), "r"(a[2]), "r"(a[3]), "r"(b0), "r"(b1));
}
#define LDSM4(r0, r1, r2, r3, addr) \
    asm volatile("ldmatrix.sync.aligned.m8n8.x4.shared.b16 {%0,%1,%2,%3}, [%4];" \
                 : "=r"(r0), "=r"(r1), "=r"(r2), "=r"(r3) : "r"(addr) : "memory")
#define LDSM2(r0, r1, addr) \
    asm volatile("ldmatrix.sync.aligned.m8n8.x2.shared.b16 {%0,%1}, [%2];" \
                 : "=r"(r0), "=r"(r1) : "r"(addr) : "memory")

extern "C" __global__ void __launch_bounds__(NTHR, 2)
hrc_mma_kernel(const float* __restrict__ x,     const float* __restrict__ kern,
               const float* __restrict__ maskw, const float* __restrict__ maskb,
               const float* __restrict__ bn_g,  const float* __restrict__ bn_b,
               const float* __restrict__ bn_m,  const float* __restrict__ bn_v,
               float* __restrict__ out)
{
    extern __shared__ char smemc[];
    float* sxf = (float*)(smemc + OFF_SX);
    float* smf = (float*)(smemc + OFF_SM);
    float* bnf = (float*)(smemc + OFF_BN);

    const int b   = blockIdx.z;
    const int h0  = blockIdx.y * TH;
    const int w0  = blockIdx.x * TW;
    const int tid = threadIdx.x;
    const int wid = tid >> 5;
    const int lid = tid & 31;

    // fragment-row mapping (phase 1 AND main GEMM)
    const int kq    = (lid & 3) * 2;
    const int px0   = wid * 16 + (lid >> 2);
    const int xoff0 = (px0 >> 5) * XP + (px0 & 31);

    // ---- load x tile (64 ch + halo), SAME zero-padding ----
    const float* xb = x + (size_t)b * CIN * HH * WW;
    for (int idx = tid; idx < CIN * XROWS * (TW + 2); idx += NTHR) {
        int ic  = idx / (XROWS * (TW + 2));
        int rem = idx - ic * (XROWS * (TW + 2));
        int r   = rem / (TW + 2);
        int c   = rem - r * (TW + 2);
        int gh = h0 - 1 + r, gw = w0 - 1 + c;
        float v = 0.f;
        if ((unsigned)gh < HH && (unsigned)gw < WW)
            v = xb[(ic * HH + gh) * WW + gw];
        sxf[(ic * XROWS + r) * XP + c] = v;
    }
    // zero MW tile area (rows 4-7 of each 8-row tile must be 0)
    for (int i = tid; i < 4608; i += NTHR) ((u32*)(smemc + OFF_W))[i] = 0;
    if (tid < COUT) {
        float s = bn_g[tid] * rsqrtf(bn_v[tid] + 1e-5f);
        bnf[tid] = s;
        bnf[64 + tid] = bn_b[tid] - bn_m[tid] * s;
    }
    __syncthreads();

    // ---- build mask-weight hi/lo tiles: 9 chunks, 8 rows (4 real + 4 zero) x 128 B ----
    for (int idx = tid; idx < RN * KTOT; idx += NTHR) {
        int r = idx / KTOT, k = idx - r * KTOT;
        int c = k >> 6, kk = k & 63;
        float v = maskw[idx];
        u32 off = (u32)(c * 1024 + ((r * 128 + kk * 2) ^ (r << 4)));
        *(unsigned short*)(smemc + OFF_W + off) =
            (unsigned short)(__float_as_uint(v) >> 16);
        float vl = v - truncf16(v);
        *(unsigned short*)(smemc + OFF_W + MW_LO + off) =
            (unsigned short)(cvt_bf2(vl, vl) & 0xFFFFu);
    }
    __syncthreads();

    // ---- phase 1: region logits via MMA -> softmax masks ----
    {
        float lg[4] = {0.f, 0.f, 0.f, 0.f};
        const u32 mwbase = smem_u32(smemc + OFF_W);
        const int rw = lid & 7, hf = (lid >> 3) & 1;
        float xv[32];
        #pragma unroll 1
        for (int c = 0; c < 9; c++) {
            #pragma unroll
            for (int ks = 0; ks < 4; ks++) {
                #pragma unroll
                for (int e = 0; e < 4; e++) {
                    int dk = (e & 1) + ((e >> 1) << 3);
                    int k  = c * 64 + ks * 16 + kq + dk;
                    int ic = (k * 7282) >> 16;
                    int t  = k - ic * 9;
                    int kh = (t * 11) >> 5;
                    int kw = t - kh * 3;
                    int off = (ic * XROWS + kh) * XP + kw + xoff0;
                    xv[ks * 8 + e * 2 + 0] = sxf[off];
                    xv[ks * 8 + e * 2 + 1] = sxf[off + 8];
                }
            }
            #pragma unroll
            for (int ks = 0; ks < 4; ks++) {
                const float* v8 = &xv[ks * 8];
                u32 ah[4], al[4];
                ah[0] = prmt7632(v8[0], v8[2]); ah[1] = prmt7632(v8[1], v8[3]);
                ah[2] = prmt7632(v8[4], v8[6]); ah[3] = prmt7632(v8[5], v8[7]);
                al[0] = cvt_bf2(v8[0] - truncf16(v8[0]), v8[2] - truncf16(v8[2]));
                al[1] = cvt_bf2(v8[1] - truncf16(v8[1]), v8[3] - truncf16(v8[3]));
                al[2] = cvt_bf2(v8[4] - truncf16(v8[4]), v8[6] - truncf16(v8[6]));
                al[3] = cvt_bf2(v8[5] - truncf16(v8[5]), v8[7] - truncf16(v8[7]));
                u32 lmo = (u32)((rw * 128 + ks * 32 + hf * 16) ^ (rw << 4)) + (u32)(c * 1024);
                u32 bh0, bh1, bl0, bl1;
                LDSM2(bh0, bh1, mwbase + lmo);
                LDSM2(bl0, bl1, mwbase + MW_LO + lmo);
                mma16816(lg, ah, bh0, bh1);   // hi*hi
                mma16816(lg, al, bh0, bh1);   // lo*hi
                mma16816(lg, ah, bl0, bl1);   // hi*lo
            }
        }
        float p0 = __shfl_xor_sync(0xffffffffu, lg[0], 1);
        float p1 = __shfl_xor_sync(0xffffffffu, lg[1], 1);
        float p2 = __shfl_xor_sync(0xffffffffu, lg[2], 1);
        float p3 = __shfl_xor_sync(0xffffffffu, lg[3], 1);
        int q = lid & 3;
        if (q < 2) {
            float l0, l1, l2, l3; int px;
            if (q == 0) { l0 = lg[0]; l1 = lg[1]; l2 = p0; l3 = p1; px = px0; }
            else        { l0 = p2; l1 = p3; l2 = lg[2]; l3 = lg[3]; px = px0 + 8; }
            l0 += maskb[0]; l1 += maskb[1]; l2 += maskb[2]; l3 += maskb[3];
            float mx = fmaxf(fmaxf(l0, l1), fmaxf(l2, l3));
            float e0 = expf(l0 - mx), e1 = expf(l1 - mx);
            float e2 = expf(l2 - mx), e3 = expf(l3 - mx);
            float inv = 1.f / (e0 + e1 + e2 + e3);
            float m[4] = {e0 * inv, e1 * inv, e2 * inv, e3 * inv};
            int prow = px >> 5, pcol = px & 31;
            #pragma unroll
            for (int r = 0; r < RN; r++) {
                smf[r * 128 + px] = m[r];
                out[MASK_BASE + ((size_t)(b * RN + r) * HH + h0 + prow) * WW + w0 + pcol] = m[r];
            }
        }
        __syncthreads();   // smf ready; MW tiles dead -> W buffers may be written
    }

    // ---- main loop: chunk-outer / region-inner; split-chain accumulators ----
    const int ocb = tid >> 2;
    const int qq  = tid & 3;
    const u32 wxm = (u32)((ocb & 7) << 4);

    const int rowbase = ((lid >> 4) << 3) + (lid & 7);
    const int q2      = (lid >> 3) & 1;
    const u32 lmxm    = (u32)((rowbase & 7) << 4);
    const u32 lmoff   = (u32)(rowbase * 128 + q2 * 16);

    const u32 wb_u32[2] = { smem_u32(smemc + OFF_W),
                            smem_u32(smemc + OFF_W + 16384) };
    char* wb_ptr[2] = { smemc + OFF_W, smemc + OFF_W + 16384 };

    const float* kb = kern + (size_t)b * RN * COUT * KTOT;

    float acc[8][4];
    #pragma unroll
    for (int n = 0; n < 8; n++)
        #pragma unroll
        for (int j = 0; j < 4; j++) acc[n][j] = 0.f;

    // prologue: stage W for iter 0 into buffer 0
    {
        const float4* gp = (const float4*)(kb + (size_t)ocb * KTOT) + (qq * 16) / 4;
        #pragma unroll
        for (int f = 0; f < 4; f++) {
            float4 v = gp[f];
            u32 o = (u32)(ocb * 128 + ((qq * 32 + f * 8) ^ wxm));
            *(uint2*)(wb_ptr[0] + o) = make_uint2(prmt7632(v.x, v.y), prmt7632(v.z, v.w));
            *(uint2*)(wb_ptr[0] + 8192 + o) = make_uint2(
                cvt_bf2(v.x - truncf16(v.x), v.y - truncf16(v.y)),
                cvt_bf2(v.z - truncf16(v.z), v.w - truncf16(v.w)));
        }
    }

    u32 ah[16], al[16];   // A fragments for 4 k-steps (unscaled, region-independent)
    #pragma unroll 1
    for (int c = 0; c < 9; c++) {
        // build A fragments for this chunk (shared across all 4 regions)
        #pragma unroll
        for (int ks = 0; ks < 4; ks++) {
            float v8[8];
            #pragma unroll
            for (int e = 0; e < 4; e++) {
                int dk = (e & 1) + ((e >> 1) << 3);      // 0,1,8,9
                int k  = c * 64 + ks * 16 + kq + dk;
                int ic = (k * 7282) >> 16;               // k/9 exact for k<576
                int t  = k - ic * 9;
                int kh = (t * 11) >> 5;                  // t/3
                int kw = t - kh * 3;
                int off = (ic * XROWS + kh) * XP + kw + xoff0;
                v8[e * 2 + 0] = sxf[off];
                v8[e * 2 + 1] = sxf[off + 8];            // row m+8
            }
            ah[ks * 4 + 0] = prmt7632(v8[0], v8[2]);
            ah[ks * 4 + 1] = prmt7632(v8[1], v8[3]);
            ah[ks * 4 + 2] = prmt7632(v8[4], v8[6]);
            ah[ks * 4 + 3] = prmt7632(v8[5], v8[7]);
            al[ks * 4 + 0] = cvt_bf2(v8[0] - truncf16(v8[0]), v8[2] - truncf16(v8[2]));
            al[ks * 4 + 1] = cvt_bf2(v8[1] - truncf16(v8[1]), v8[3] - truncf16(v8[3]));
            al[ks * 4 + 2] = cvt_bf2(v8[4] - truncf16(v8[4]), v8[6] - truncf16(v8[6]));
            al[ks * 4 + 3] = cvt_bf2(v8[5] - truncf16(v8[5]), v8[7] - truncf16(v8[7]));
        }

        #pragma unroll
        for (int r = 0; r < 4; r++) {
            const int i = c * 4 + r;
            __syncthreads();                 // buf(i&1) visible; prior readers done

            // prefetch next W stage into registers (LDG latency overlapped with MMA)
            float4 wn[4];
            const bool hasnext = (i + 1 < NITER);
            if (hasnext) {
                const int rn = (i + 1) & 3, cn = (i + 1) >> 2;
                const float4* gp = (const float4*)(kb + ((size_t)(rn * COUT) + ocb) * KTOT)
                                   + (cn * 64 + qq * 16) / 4;
                #pragma unroll
                for (int f = 0; f < 4; f++) wn[f] = gp[f];
            }

            const float m0 = smf[r * 128 + px0];
            const float m1 = smf[r * 128 + px0 + 8];
            const u32 whi = wb_u32[i & 1];

            // per n-tile pair: split chains (hh depth 4, cross depth 8), then mask-fold
            #pragma unroll
            for (int ntp = 0; ntp < 4; ntp++) {
                float hh0[4] = {0.f, 0.f, 0.f, 0.f};
                float hh1[4] = {0.f, 0.f, 0.f, 0.f};
                float tx0[4] = {0.f, 0.f, 0.f, 0.f};
                float tx1[4] = {0.f, 0.f, 0.f, 0.f};
                #pragma unroll
                for (int ks = 0; ks < 4; ks++) {
                    u32 ad = whi + (u32)(ntp * 2048) + ((lmoff + (u32)(ks * 32)) ^ lmxm);
                    u32 bh0, bh1, bh2, bh3, bl0, bl1, bl2, bl3;
                    LDSM4(bh0, bh1, bh2, bh3, ad);
                    LDSM4(bl0, bl1, bl2, bl3, ad + 8192);
                    const u32* ahk = &ah[ks * 4];
                    const u32* alk = &al[ks * 4];
                    mma16816(hh0, ahk, bh0, bh1);   // hi*hi -> hh chain
                    mma16816(hh1, ahk, bh2, bh3);
                    mma16816(tx0, alk, bh0, bh1);   // lo*hi -> cross chain
                    mma16816(tx1, alk, bh2, bh3);
                    mma16816(tx0, ahk, bl0, bl1);   // hi*lo -> cross chain
                    mma16816(tx1, ahk, bl2, bl3);
                }
                float* a0 = acc[ntp * 2];
                float* a1 = acc[ntp * 2 + 1];
                a0[0] = fmaf(m0, hh0[0], fmaf(m0, tx0[0], a0[0]));
                a0[1] = fmaf(m0, hh0[1], fmaf(m0, tx0[1], a0[1]));
                a0[2] = fmaf(m1, hh0[2], fmaf(m1, tx0[2], a0[2]));
                a0[3] = fmaf(m1, hh0[3], fmaf(m1, tx0[3], a0[3]));
                a1[0] = fmaf(m0, hh1[0], fmaf(m0, tx1[0], a1[0]));
                a1[1] = fmaf(m0, hh1[1], fmaf(m0, tx1[1], a1[1]));
                a1[2] = fmaf(m1, hh1[2], fmaf(m1, tx1[2], a1[2]));
                a1[3] = fmaf(m1, hh1[3], fmaf(m1, tx1[3], a1[3]));
            }

            // convert + store next W stage into the other buffer
            if (hasnext) {
                char* hb = wb_ptr[(i + 1) & 1];
                #pragma unroll
                for (int f = 0; f < 4; f++) {
                    float4 v = wn[f];
                    u32 o = (u32)(ocb * 128 + ((qq * 32 + f * 8) ^ wxm));
                    *(uint2*)(hb + o) = make_uint2(prmt7632(v.x, v.y), prmt7632(v.z, v.w));
                    *(uint2*)(hb + 8192 + o) = make_uint2(
                        cvt_bf2(v.x - truncf16(v.x), v.y - truncf16(v.y)),
                        cvt_bf2(v.z - truncf16(v.z), v.w - truncf16(v.w)));
                }
            }
        }
    }

    // ---- epilogue: transpose through smem (reuse sx), BN + ReLU, coalesced stores ----
    float* S = sxf;
    #pragma unroll
    for (int nt = 0; nt < 8; nt++) {
        int col = nt * 8 + (lid & 3) * 2;
        S[px0 * 67 + col]           = acc[nt][0];
        S[px0 * 67 + col + 1]       = acc[nt][1];
        S[(px0 + 8) * 67 + col]     = acc[nt][2];
        S[(px0 + 8) * 67 + col + 1] = acc[nt][3];
    }
    __syncthreads();
    const size_t ob = (size_t)b * COUT * HH * WW;
    const int lanepos = tid & 7;
    #pragma unroll
    for (int i = 0; i < 8; i++) {
        int line = (tid >> 3) + 32 * i;          // 0..255
        int oc = line & 63, prow = line >> 6;
        float sc = bnf[oc], sh = bnf[64 + oc];
        int rb = prow * 32 + lanepos * 4;
        float4 v;
        v.x = fmaxf(fmaf(S[(rb + 0) * 67 + oc], sc, sh), 0.f);
        v.y = fmaxf(fmaf(S[(rb + 1) * 67 + oc], sc, sh), 0.f);
        v.z = fmaxf(fmaf(S[(rb + 2) * 67 + oc], sc, sh), 0.f);
        v.w = fmaxf(fmaf(S[(rb + 3) * 67 + oc], sc, sh), 0.f);
        *(float4*)&out[ob + (size_t)oc * (HH * WW) + (size_t)(h0 + prow) * WW
                       + w0 + lanepos * 4] = v;
    }
}

extern "C" void kernel_launch(void* const* d_in, const int* in_sizes, int n_in,
                              void* d_out, int out_size)
{
    const float* x  = (const float*)d_in[0];
    const float* k  = (const float*)d_in[1];
    const float* mw = (const float*)d_in[2];
    const float* mb = (const float*)d_in[3];
    const float* g  = (const float*)d_in[4];
    const float* be = (const float*)d_in[5];
    const float* mn = (const float*)d_in[6];
    const float* vr = (const float*)d_in[7];

    cudaFuncSetAttribute(hrc_mma_kernel, cudaFuncAttributeMaxDynamicSharedMemorySize,
                         SMEM_BYTES);

    dim3 grid(WW / TW, HH / TH, BB);   // 4 x 32 x 8 = 1024 blocks
    hrc_mma_kernel<<<grid, NTHR, SMEM_BYTES>>>(x, k, mw, mb, g, be, mn, vr, (float*)d_out);
}